// round 14
// baseline (speedup 1.0000x reference)
#include <cuda_runtime.h>
#include <cuda_bf16.h>
#include <cuda_fp16.h>
#include <cstdint>

#define BB   64
#define EMBD 256
#define HIDD 512
#define VOC  32000
#define TT   64

typedef unsigned long long ull;

// ---------------- scratch (device globals; no allocation) ----------------
__device__ __align__(16) float g_hbuf[2][BB * HIDD];
__device__ __align__(16) float g_cbuf[BB * HIDD];
// A operand fp16, chunk-major + pre-swizzled: [kchunk 0..7][8KB chunk]
__device__ __align__(16) __half g_haf16[64 * HIDD];
// W operand fp16, chunk-major + pre-swizzled: [nb 0..249][kchunk 0..7][16KB chunk]
__device__ __align__(16) __half g_wf16[(size_t)VOC * HIDD];
// W_hh @ h(t) partials, computed one step ahead: [gate-row 0..2047][batch 0..63]
__device__ __align__(16) float g_hhpart[4 * HIDD * BB];
__device__ ull  g_blockmax[250][BB];   // per-(n-block, row) approx max keys
__device__ ull  g_amaxE[TT][BB];       // exact keys (from fixup)
__device__ int  g_tmode[1];

// ---------------- scalar helpers ----------------
__device__ __forceinline__ ull ffma2(ull a, ull b, ull c) {
    ull d;
    asm("fma.rn.f32x2 %0, %1, %2, %3;" : "=l"(d) : "l"(a), "l"(b), "l"(c));
    return d;
}
__device__ __forceinline__ float sigm_acc(float x) { return 1.0f / (2.0f + expm1f(-x)); }
__device__ __forceinline__ float tanh_acc(float x) {
    float ax = fabsf(x);
    if (ax > 9.0f) return copysignf(1.0f, x);
    float e = expm1f(2.0f * ax);
    return copysignf(e / (e + 2.0f), x);
}
__device__ __forceinline__ ull pack_key(float v, int n) {
    unsigned u = __float_as_uint(v);
    u = (u & 0x80000000u) ? ~u : (u | 0x80000000u);
    return ((ull)u << 32) | (ull)(0xFFFFFFFFu - (unsigned)n);
}
__device__ __forceinline__ float unpack_val(ull key) {
    unsigned u = (unsigned)(key >> 32);
    return (u & 0x80000000u) ? __uint_as_float(u ^ 0x80000000u) : __uint_as_float(~u);
}
__device__ __forceinline__ uint32_t smem_u32(const void* p) {
    uint32_t a;
    asm("{ .reg .u64 t; cvta.to.shared.u64 t, %1; cvt.u32.u64 %0, t; }" : "=r"(a) : "l"(p));
    return a;
}

// ---------------- mma / ldmatrix / bulk-async (sm_90 baseline PTX) -----------
#define SWZ(o) ((o) ^ (((o) >> 3) & 0x70))
#define LDSM4(r0, r1, r2, r3, addr) \
    asm volatile("ldmatrix.sync.aligned.m8n8.x4.shared.b16 {%0,%1,%2,%3}, [%4];" \
        : "=r"(r0), "=r"(r1), "=r"(r2), "=r"(r3) : "r"(addr))
#define MMA16816(d, a, b0, b1) \
    asm volatile("mma.sync.aligned.m16n8k16.row.col.f32.f16.f16.f32 " \
        "{%0,%1,%2,%3},{%4,%5,%6,%7},{%8,%9},{%0,%1,%2,%3};" \
        : "+f"((d)[0]), "+f"((d)[1]), "+f"((d)[2]), "+f"((d)[3]) \
        : "r"((a)[0]), "r"((a)[1]), "r"((a)[2]), "r"((a)[3]), "r"(b0), "r"(b1))
#define FENCE_ASYNC()     asm volatile("fence.proxy.async.shared::cta;" ::: "memory")
#define MBAR_INIT(mb, c)  asm volatile("mbarrier.init.shared.b64 [%0], %1;" :: "r"(mb), "r"((uint32_t)(c)) : "memory")
#define MBAR_EXPECT_TX(mb, bytes) \
    asm volatile("mbarrier.arrive.expect_tx.shared.b64 _, [%0], %1;" :: "r"(mb), "r"((uint32_t)(bytes)) : "memory")
#define BULK_G2S(dst, src, size, mb) \
    asm volatile("cp.async.bulk.shared::cta.global.mbarrier::complete_tx::bytes [%0], [%1], %2, [%3];" \
        :: "r"(dst), "l"(src), "r"((uint32_t)(size)), "r"(mb) : "memory")
#define MBAR_WAIT(mb, par) do {                                                  \
    uint32_t _mb = (mb), _p = (par), _d;                                         \
    asm volatile("{ .reg .pred p; mbarrier.try_wait.parity.acquire.cta.shared::cta.b64 p, [%1], %2; selp.b32 %0, 1, 0, p; }" \
        : "=r"(_d) : "r"(_mb), "r"(_p) : "memory");                              \
    if (!_d) {                                                                   \
        asm volatile("{ .reg .pred P1; WL_%=: mbarrier.try_wait.parity.acquire.cta.shared::cta.b64 P1, [%0], %1, 0x989680; @P1 bra.uni WD_%=; bra.uni WL_%=; WD_%=: }" \
            :: "r"(_mb), "r"(_p) : "memory");                                    \
    }                                                                            \
} while (0)

// ---------------- hh role: exact fp32 W_hh @ h -> g_hhpart -------------------
// 32 role blocks, block 256. Block b2 covers gate-rows b2*64 .. +63, all 64 batch.
// K=512 in 4 chunks of 128. smem: s_x 32KB @0, s_w 32KB @32768 (needs >= 64KB dyn).
__device__ void hh_role(const float* __restrict__ h, const float* __restrict__ w_hh,
                        int b2, char* smem) {
    ulonglong2* s_x = (ulonglong2*)smem;               // [64 rows][32 quads]
    ulonglong2* s_w = (ulonglong2*)(smem + 32768);     // [64 rows][32 quads]
    const int tid  = threadIdx.x;
    const int w    = tid >> 5;
    const int lane = tid & 31;
    const int mg   = lane >> 2;      // batch group of 8
    const int rq   = lane & 3;       // row pair selector

    ull acc[8][2];
#pragma unroll
    for (int i = 0; i < 8; ++i) { acc[i][0] = 0ull; acc[i][1] = 0ull; }

#pragma unroll
    for (int kc = 0; kc < 4; ++kc) {
        __syncthreads();
#pragma unroll
        for (int it = 0; it < 8; ++it) {
            int idx = tid + it * 256;                  // 0..2047
            int m = idx >> 5, kq = idx & 31;
            float4 v = *(const float4*)&h[(size_t)m * HIDD + kc * 128 + kq * 4];
            s_x[m * 32 + (kq ^ (m >> 3))] = *(ulonglong2*)&v;
        }
#pragma unroll
        for (int it = 0; it < 8; ++it) {
            int idx = tid + it * 256;
            int r = idx >> 5, kq = idx & 31;
            float4 v = *(const float4*)&w_hh[(size_t)(b2 * 64 + r) * HIDD + kc * 128 + kq * 4];
            s_w[r * 32 + (kq ^ (r & 7))] = *(ulonglong2*)&v;
        }
        __syncthreads();
#pragma unroll
        for (int q = 0; q < 32; ++q) {
            ulonglong2 xv[8], wv[2];
#pragma unroll
            for (int i = 0; i < 8; ++i) xv[i] = s_x[(mg * 8 + i) * 32 + (q ^ mg)];
#pragma unroll
            for (int j = 0; j < 2; ++j) {
                int rl = rq * 2 + j;
                wv[j] = s_w[(w * 8 + rl) * 32 + (q ^ rl)];
            }
#pragma unroll
            for (int i = 0; i < 8; ++i)
#pragma unroll
                for (int j = 0; j < 2; ++j) {
                    acc[i][j] = ffma2(xv[i].x, wv[j].x, acc[i][j]);
                    acc[i][j] = ffma2(xv[i].y, wv[j].y, acc[i][j]);
                }
        }
    }
#pragma unroll
    for (int i = 0; i < 8; ++i)
#pragma unroll
        for (int j = 0; j < 2; ++j) {
            float2 p = *(float2*)&acc[i][j];
            int R = b2 * 64 + w * 8 + rq * 2 + j;
            g_hhpart[(size_t)R * 64 + mg * 8 + i] = p.x + p.y;
        }
}

// ---------------- init (+ hh role for t=0) ----------------
#define INIT_SMEM 65536
__global__ void __launch_bounds__(256)
init_kernel(const float* __restrict__ eh, const float* __restrict__ ec,
            const int* __restrict__ tgt_i32, const float* __restrict__ w_hh) {
    extern __shared__ char smem[];
    if (blockIdx.x >= 128) {              // role blocks: W_hh @ h(0) = encoder_h
        hh_role(eh, w_hh, blockIdx.x - 128, smem);
        return;
    }
    int idx = blockIdx.x * blockDim.x + threadIdx.x;
    if (idx < BB * HIDD) {
        g_hbuf[0][idx] = eh[idx];
        g_cbuf[idx]    = ec[idx];
    }
    if (idx < TT * BB) ((ull*)g_amaxE)[idx] = 0ull;
    if (idx == 0)
        g_tmode[0] = ((tgt_i32[1] | tgt_i32[3] | tgt_i32[5] | tgt_i32[7]) == 0) ? 1 : 0;
}

// ---------------- fc_w -> fp16, 128-row chunks + swizzled --------------------
__global__ void __launch_bounds__(256) wsplit_kernel(const float* __restrict__ fc_w) {
    size_t u = (size_t)blockIdx.x * 256 + threadIdx.x;    // 0 .. 2,047,999
    int n  = (int)(u >> 6);
    int k8 = (int)(u & 63);
    const float4* src = (const float4*)(fc_w + (size_t)n * HIDD + k8 * 8);
    float4 v0 = src[0], v1 = src[1];
    float f[8] = {v0.x, v0.y, v0.z, v0.w, v1.x, v1.y, v1.z, v1.w};
    unsigned short hw[8];
#pragma unroll
    for (int i = 0; i < 8; ++i) hw[i] = __half_as_ushort(__float2half_rn(f[i]));
    uint4 H;
    H.x = hw[0] | ((uint32_t)hw[1] << 16); H.y = hw[2] | ((uint32_t)hw[3] << 16);
    H.z = hw[4] | ((uint32_t)hw[5] << 16); H.w = hw[6] | ((uint32_t)hw[7] << 16);
    int nb = n >> 7, rown = n & 127, kch = k8 >> 3, ks = k8 & 7;
    size_t cb = ((size_t)nb * 8 + kch) * 16384;
    uint32_t off = SWZ((uint32_t)(rown * 128 + ks * 16));
    *(uint4*)((char*)g_wf16 + cb + off) = H;
}

// ---------------- gates: emb GEMM + hh partials + LSTM pointwise -------------
// grid 128 (4 hidden cols -> 16 gate-rows), block 256. Phase-2 (hh) is now
// precomputed into g_hhpart by fc(t-1)/init role blocks.
#define G_SMEM_BYTES (197120 + 256)

__global__ void __launch_bounds__(256)
gates_kernel(int t,
             const long long* __restrict__ tgt64, const int* __restrict__ tgt32,
             const int* __restrict__ tf_mask,
             const float* __restrict__ emb,
             const float* __restrict__ w_ih,
             const float* __restrict__ b_ih, const float* __restrict__ b_hh) {
    extern __shared__ char smem[];
    ulonglong2* s_hx = (ulonglong2*)smem;
    ulonglong2* s_w  = (ulonglong2*)(smem + 131072);
    float (*s_part)[16][65] = (float (*)[16][65])(smem + 163840);
    int* s_inp = (int*)(smem + 197120);

    const int tid  = threadIdx.x;
    const int j0   = blockIdx.x * 4;
    const int w    = tid >> 5;
    const int lane = tid & 31;
    const int mg   = lane >> 2;
    const int rq   = lane & 3;

    if (tid < BB) {
        int inp = 0;
        if (t > 0) {
            if (tf_mask[t - 1] > 0) {
                inp = g_tmode[0] ? (int)tgt64[(size_t)tid * TT + (t - 1)]
                                 : tgt32[(size_t)tid * TT + (t - 1)];
            } else {
                ull p = g_amaxE[t - 1][tid];
                inp = (int)(0xFFFFFFFFu - (unsigned)(p & 0xFFFFFFFFull));
            }
        }
        s_inp[tid] = inp;
    }
    __syncthreads();

    ull acc[8][4];
#pragma unroll
    for (int i = 0; i < 8; ++i)
#pragma unroll
        for (int j = 0; j < 4; ++j) acc[i][j] = 0ull;

    // emb GEMM, K=256
#pragma unroll
    for (int it = 0; it < 16; ++it) {
        int idx = tid + it * 256;
        int m = idx >> 6, kq = idx & 63;
        float4 v = *(const float4*)&emb[(size_t)s_inp[m] * EMBD + kq * 4];
        s_hx[m * 64 + (kq ^ (m >> 3))] = *(ulonglong2*)&v;
    }
#pragma unroll
    for (int it = 0; it < 4; ++it) {
        int idx = tid + it * 256;
        int rr = idx >> 6, kq = idx & 63;
        int R  = (rr >> 2) * HIDD + j0 + (rr & 3);
        float4 v = *(const float4*)&w_ih[(size_t)R * EMBD + kq * 4];
        s_w[rr * 64 + (kq ^ (rr >> 2))] = *(ulonglong2*)&v;
    }
    __syncthreads();
#pragma unroll
    for (int q8 = 0; q8 < 8; ++q8) {
        int q = w * 8 + q8;
        ulonglong2 xv[8], wv[4];
#pragma unroll
        for (int i = 0; i < 8; ++i) xv[i] = s_hx[(mg * 8 + i) * 64 + (q ^ mg)];
#pragma unroll
        for (int j = 0; j < 4; ++j) wv[j] = s_w[(rq * 4 + j) * 64 + (q ^ rq)];
#pragma unroll
        for (int i = 0; i < 8; ++i)
#pragma unroll
            for (int j = 0; j < 4; ++j) {
                acc[i][j] = ffma2(xv[i].x, wv[j].x, acc[i][j]);
                acc[i][j] = ffma2(xv[i].y, wv[j].y, acc[i][j]);
            }
    }

#pragma unroll
    for (int i = 0; i < 8; ++i)
#pragma unroll
        for (int j = 0; j < 4; ++j) {
            float2 p = *(float2*)&acc[i][j];
            s_part[w][rq * 4 + j][mg * 8 + i] = p.x + p.y;
        }
    __syncthreads();

    {
        int m  = tid & 63;
        int jj = tid >> 6;
        float gv4[4];
#pragma unroll
        for (int g = 0; g < 4; ++g) {
            float s = 0.f;
#pragma unroll
            for (int w8 = 0; w8 < 8; ++w8) s += s_part[w8][g * 4 + jj][m];
            int R = g * HIDD + j0 + jj;
            gv4[g] = s + g_hhpart[(size_t)R * 64 + m] + b_ih[R] + b_hh[R];
        }
        float iv = sigm_acc(gv4[0]);
        float fv = sigm_acc(gv4[1]);
        float gg = tanh_acc(gv4[2]);
        float ov = sigm_acc(gv4[3]);
        int j = j0 + jj;
        float c0 = g_cbuf[(size_t)m * HIDD + j];
        float c1 = fv * c0 + iv * gg;
        float h1 = ov * tanh_acc(c1);
        g_cbuf[(size_t)m * HIDD + j]              = c1;
        g_hbuf[(t + 1) & 1][(size_t)m * HIDD + j] = h1;
        int kch = j >> 6, kc = j & 63, ks = kc >> 3, b2 = kc & 7;
        *(__half*)((char*)g_haf16 + (size_t)kch * 8192
                   + SWZ((uint32_t)(m * 128 + ks * 16)) + b2 * 2) = __float2half_rn(h1);
    }
}

// ---------------- fc mma fp16 + hh role blocks for next step -----------------
// grid 282: blocks 0..31 = hh role (W_hh @ h(t+1) -> g_hhpart for step t+1),
// blocks 32..281 = fc tiles (nb = blockIdx-32). 4-stage bulk pipeline.
// smem: stages [0, 4*24576) | bias @98304 | amax @98816 | mbar[4] @99328
#define FC_STG  24576
#define FC_SMEM 99392

__global__ void __launch_bounds__(256)
fc_mma_kernel(int t, const float* __restrict__ fc_b, const float* __restrict__ w_hh,
              float* __restrict__ out) {
    extern __shared__ char smem[];
    if (blockIdx.x < 32) {                 // hh role for step t+1
        hh_role(g_hbuf[(t + 1) & 1], w_hh, blockIdx.x, smem);
        return;
    }
    const uint32_t sbase = smem_u32(smem);
    float* s_bias = (float*)(smem + 98304);
    ull*   s_amax = (ull*)(smem + 98816);
    const uint32_t mb0 = sbase + 99328;

    const int tid  = threadIdx.x;
    const int w    = tid >> 5;
    const int lane = tid & 31;
    const int wm   = w & 3;
    const int wn   = w >> 2;
    const int nb   = blockIdx.x - 32;
    const int row16 = lane & 15;
    const int kseg  = lane >> 4;

    if (tid < 128) s_bias[tid] = fc_b[nb * 128 + tid];
    if (tid < 64)  s_amax[tid] = 0ull;
    if (tid < 4)   MBAR_INIT(mb0 + tid * 8, 1);
    __syncthreads();
    FENCE_ASYNC();

    auto issue = [&](int c) {
        int s = c & 3;
        uint32_t mb = mb0 + s * 8;
        MBAR_EXPECT_TX(mb, 24576);
        const char* ap = (const char*)g_haf16 + (size_t)c * 8192;
        const char* wp = (const char*)g_wf16 + ((size_t)nb * 8 + c) * 16384;
        BULK_G2S(sbase + s * FC_STG, ap, 8192, mb);
        BULK_G2S(sbase + s * FC_STG + 8192, wp, 16384, mb);
    };
    if (tid == 0) { issue(0); issue(1); issue(2); issue(3); }

    float acc[8][4];
#pragma unroll
    for (int fj = 0; fj < 8; ++fj)
#pragma unroll
        for (int e = 0; e < 4; ++e) acc[fj][e] = 0.f;

    int par[4] = {0, 0, 0, 0};
    for (int c = 0; c < 8; ++c) {
        int s = c & 3;
        MBAR_WAIT(mb0 + s * 8, par[s]);
        par[s] ^= 1;
        const uint32_t aBase = sbase + s * FC_STG;
        const uint32_t wBase = aBase + 8192;
#pragma unroll
        for (int kf = 0; kf < 4; ++kf) {
            uint32_t aH[4];
            LDSM4(aH[0], aH[1], aH[2], aH[3],
                  aBase + SWZ((uint32_t)((wm * 16 + row16) * 128 + kf * 32 + kseg * 16)));
#pragma unroll
            for (int j = 0; j < 4; ++j) {
                uint32_t b[4];
                LDSM4(b[0], b[1], b[2], b[3],
                      wBase + SWZ((uint32_t)((wn * 64 + j * 16 + row16) * 128 + kf * 32 + kseg * 16)));
                MMA16816(acc[j * 2 + 0], aH, b[0], b[2]);
                MMA16816(acc[j * 2 + 1], aH, b[1], b[3]);
            }
        }
        __syncthreads();
        if (tid == 0 && c + 4 < 8) issue(c + 4);
    }

    // ---- epilogue: bias, store, per-block approx argmax keys ----
    const int r0 = wm * 16 + (lane >> 2);
    ull best0 = 0ull, best1 = 0ull;
#pragma unroll
    for (int fj = 0; fj < 8; ++fj) {
        int cb = wn * 64 + fj * 8 + (lane & 3) * 2;
        int n  = nb * 128 + cb;
        float v0 = acc[fj][0] + s_bias[cb];
        float v1 = acc[fj][1] + s_bias[cb + 1];
        float v2 = acc[fj][2] + s_bias[cb];
        float v3 = acc[fj][3] + s_bias[cb + 1];
        *(float2*)&out[((size_t)r0 * TT + t) * VOC + n]       = make_float2(v0, v1);
        *(float2*)&out[((size_t)(r0 + 8) * TT + t) * VOC + n] = make_float2(v2, v3);
        ull k0 = pack_key(v0, n), k1 = pack_key(v1, n + 1);
        ull k2 = pack_key(v2, n), k3 = pack_key(v3, n + 1);
        if (k1 > k0) k0 = k1;
        if (k3 > k2) k2 = k3;
        if (k0 > best0) best0 = k0;
        if (k2 > best1) best1 = k2;
    }
    atomicMax(&s_amax[r0], best0);
    atomicMax(&s_amax[r0 + 8], best1);
    __syncthreads();
    if (tid < 64) g_blockmax[nb][tid] = s_amax[tid];   // plain store, sole writer
}

// ---------------- argmax fixup: blockmax scan + exact fp32 re-check ----------
// grid 64 (one block per batch row), block 256.
__global__ void __launch_bounds__(256)
fixup_kernel(int t, const float* __restrict__ fc_w, const float* __restrict__ fc_b,
             const float* __restrict__ out) {
    __shared__ float s_h[HIDD];
    __shared__ ull s_red[256];
    __shared__ float s_thresh;
    const int m = blockIdx.x, tid = threadIdx.x;
    const float* hsrc = g_hbuf[(t + 1) & 1] + (size_t)m * HIDD;
    s_h[tid] = hsrc[tid];
    s_h[256 + tid] = hsrc[256 + tid];

    ull key = (tid < 250) ? g_blockmax[tid][m] : 0ull;
    s_red[tid] = key;
    __syncthreads();
#pragma unroll
    for (int s = 128; s > 0; s >>= 1) {
        if (tid < s && s_red[tid + s] > s_red[tid]) s_red[tid] = s_red[tid + s];
        __syncthreads();
    }
    if (tid == 0) s_thresh = unpack_val(s_red[0]) - 1e-2f;
    __syncthreads();
    const float thresh = s_thresh;

    ull best = 0ull;
    if (tid < 250 && unpack_val(key) >= thresh) {
        const float* row = out + ((size_t)m * TT + t) * VOC + tid * 128;
#pragma unroll 4
        for (int i = 0; i < 128; ++i) {
            float v = row[i];
            if (v >= thresh) {
                int n = tid * 128 + i;
                const ull* hp = (const ull*)s_h;
                const ull* wp = (const ull*)(fc_w + (size_t)n * HIDD);
                ull acc = 0ull;
#pragma unroll 8
                for (int kk = 0; kk < 256; ++kk) acc = ffma2(hp[kk], wp[kk], acc);
                float2 p = *(float2*)&acc;
                ull k = pack_key(p.x + p.y + fc_b[n], n);
                if (k > best) best = k;
            }
        }
    }
    s_red[tid] = best;
    __syncthreads();
#pragma unroll
    for (int s = 128; s > 0; s >>= 1) {
        if (tid < s && s_red[tid + s] > s_red[tid]) s_red[tid] = s_red[tid + s];
        __syncthreads();
    }
    if (tid == 0) g_amaxE[t][m] = s_red[0];   // plain store, sole writer
}

// ---------------- final h/c tail ----------------
__global__ void final_kernel(float* __restrict__ out, int out_size) {
    int idx = blockIdx.x * blockDim.x + threadIdx.x;
    const size_t base = (size_t)BB * TT * VOC;
    if ((size_t)out_size >= base + 2ull * BB * HIDD) {
        if (idx < BB * HIDD) {
            out[base + idx]             = g_hbuf[0][idx];
            out[base + BB * HIDD + idx] = g_cbuf[idx];
        }
    }
}

// ---------------- launch ----------------
extern "C" void kernel_launch(void* const* d_in, const int* in_sizes, int n_in,
                              void* d_out, int out_size) {
    const float* encoder_h = (const float*)d_in[0];
    const float* encoder_c = (const float*)d_in[1];
    const void*  target    = d_in[2];
    const int*   tf_mask   = (const int*)d_in[3];
    const float* embedding = (const float*)d_in[4];
    const float* w_ih      = (const float*)d_in[5];
    const float* w_hh      = (const float*)d_in[6];
    const float* b_ih      = (const float*)d_in[7];
    const float* b_hh      = (const float*)d_in[8];
    const float* fc_w      = (const float*)d_in[9];
    const float* fc_b      = (const float*)d_in[10];
    float* out = (float*)d_out;

    cudaFuncSetAttribute(init_kernel,
                         cudaFuncAttributeMaxDynamicSharedMemorySize, INIT_SMEM);
    cudaFuncSetAttribute(gates_kernel,
                         cudaFuncAttributeMaxDynamicSharedMemorySize, G_SMEM_BYTES);
    cudaFuncSetAttribute(fc_mma_kernel,
                         cudaFuncAttributeMaxDynamicSharedMemorySize, FC_SMEM);

    init_kernel<<<160, 256, INIT_SMEM>>>(encoder_h, encoder_c, (const int*)target, w_hh);
    wsplit_kernel<<<8000, 256>>>(fc_w);
    for (int t = 0; t < TT; ++t) {
        gates_kernel<<<128, 256, G_SMEM_BYTES>>>(t, (const long long*)target,
                                                 (const int*)target, tf_mask, embedding,
                                                 w_ih, b_ih, b_hh);
        fc_mma_kernel<<<282, 256, FC_SMEM>>>(t, fc_b, w_hh, out);
        fixup_kernel<<<64, 256>>>(t, fc_w, fc_b, out);
    }
    final_kernel<<<128, 256>>>(out, out_size);
}

// round 17
// speedup vs baseline: 1.2508x; 1.2508x over previous
#include <cuda_runtime.h>
#include <cuda_bf16.h>
#include <cuda_fp16.h>
#include <cstdint>

#define BB   64
#define EMBD 256
#define HIDD 512
#define VOC  32000
#define TT   64

typedef unsigned long long ull;

// ---------------- scratch (device globals; no allocation) ----------------
__device__ __align__(16) float g_hbuf[2][BB * HIDD];
__device__ __align__(16) float g_cbuf[BB * HIDD];
// A operand fp16, chunk-major + pre-swizzled: [kchunk 0..7][8KB chunk]
__device__ __align__(16) __half g_haf16[64 * HIDD];
// W operand fp16, chunk-major + pre-swizzled: [nb 0..249][kchunk 0..7][16KB chunk]
__device__ __align__(16) __half g_wf16[(size_t)VOC * HIDD];
// W_hh @ h(t) partials, computed one step ahead: [gate-row 0..2047][batch 0..63]
__device__ __align__(16) float g_hhpart[4 * HIDD * BB];
__device__ ull  g_blockmax[250][BB];   // per-(n-block, row) approx max keys
__device__ ull  g_amaxE[TT][BB];       // exact keys (from fixup)
__device__ int  g_tmode[1];

// ---------------- scalar helpers ----------------
__device__ __forceinline__ ull ffma2(ull a, ull b, ull c) {
    ull d;
    asm("fma.rn.f32x2 %0, %1, %2, %3;" : "=l"(d) : "l"(a), "l"(b), "l"(c));
    return d;
}
__device__ __forceinline__ float sigm_acc(float x) { return 1.0f / (2.0f + expm1f(-x)); }
__device__ __forceinline__ float tanh_acc(float x) {
    float ax = fabsf(x);
    if (ax > 9.0f) return copysignf(1.0f, x);
    float e = expm1f(2.0f * ax);
    return copysignf(e / (e + 2.0f), x);
}
__device__ __forceinline__ ull pack_key(float v, int n) {
    unsigned u = __float_as_uint(v);
    u = (u & 0x80000000u) ? ~u : (u | 0x80000000u);
    return ((ull)u << 32) | (ull)(0xFFFFFFFFu - (unsigned)n);
}
__device__ __forceinline__ float unpack_val(ull key) {
    unsigned u = (unsigned)(key >> 32);
    return (u & 0x80000000u) ? __uint_as_float(u ^ 0x80000000u) : __uint_as_float(~u);
}
__device__ __forceinline__ uint32_t smem_u32(const void* p) {
    uint32_t a;
    asm("{ .reg .u64 t; cvta.to.shared.u64 t, %1; cvt.u32.u64 %0, t; }" : "=r"(a) : "l"(p));
    return a;
}

// ---------------- mma / ldmatrix / bulk-async (sm_90 baseline PTX) -----------
#define SWZ(o) ((o) ^ (((o) >> 3) & 0x70))
#define LDSM4(r0, r1, r2, r3, addr) \
    asm volatile("ldmatrix.sync.aligned.m8n8.x4.shared.b16 {%0,%1,%2,%3}, [%4];" \
        : "=r"(r0), "=r"(r1), "=r"(r2), "=r"(r3) : "r"(addr))
#define MMA16816(d, a, b0, b1) \
    asm volatile("mma.sync.aligned.m16n8k16.row.col.f32.f16.f16.f32 " \
        "{%0,%1,%2,%3},{%4,%5,%6,%7},{%8,%9},{%0,%1,%2,%3};" \
        : "+f"((d)[0]), "+f"((d)[1]), "+f"((d)[2]), "+f"((d)[3]) \
        : "r"((a)[0]), "r"((a)[1]), "r"((a)[2]), "r"((a)[3]), "r"(b0), "r"(b1))
#define FENCE_ASYNC()     asm volatile("fence.proxy.async.shared::cta;" ::: "memory")
#define MBAR_INIT(mb, c)  asm volatile("mbarrier.init.shared.b64 [%0], %1;" :: "r"(mb), "r"((uint32_t)(c)) : "memory")
#define MBAR_EXPECT_TX(mb, bytes) \
    asm volatile("mbarrier.arrive.expect_tx.shared.b64 _, [%0], %1;" :: "r"(mb), "r"((uint32_t)(bytes)) : "memory")
#define BULK_G2S(dst, src, size, mb) \
    asm volatile("cp.async.bulk.shared::cta.global.mbarrier::complete_tx::bytes [%0], [%1], %2, [%3];" \
        :: "r"(dst), "l"(src), "r"((uint32_t)(size)), "r"(mb) : "memory")
#define MBAR_WAIT(mb, par) do {                                                  \
    uint32_t _mb = (mb), _p = (par), _d;                                         \
    asm volatile("{ .reg .pred p; mbarrier.try_wait.parity.acquire.cta.shared::cta.b64 p, [%1], %2; selp.b32 %0, 1, 0, p; }" \
        : "=r"(_d) : "r"(_mb), "r"(_p) : "memory");                              \
    if (!_d) {                                                                   \
        asm volatile("{ .reg .pred P1; WL_%=: mbarrier.try_wait.parity.acquire.cta.shared::cta.b64 P1, [%0], %1, 0x989680; @P1 bra.uni WD_%=; bra.uni WL_%=; WD_%=: }" \
            :: "r"(_mb), "r"(_p) : "memory");                                    \
    }                                                                            \
} while (0)

// ---------------- hh role: exact fp32 W_hh @ h -> g_hhpart -------------------
// 32 role blocks, block 256. Block b2 covers gate-rows b2*64 .. +63, all 64 batch.
// K=512 in 4 chunks of 128. smem: s_x 32KB @0, s_w 32KB @32768 (needs >= 64KB dyn).
__device__ void hh_role(const float* __restrict__ h, const float* __restrict__ w_hh,
                        int b2, char* smem) {
    ulonglong2* s_x = (ulonglong2*)smem;               // [64 rows][32 quads]
    ulonglong2* s_w = (ulonglong2*)(smem + 32768);     // [64 rows][32 quads]
    const int tid  = threadIdx.x;
    const int w    = tid >> 5;
    const int lane = tid & 31;
    const int mg   = lane >> 2;      // batch group of 8
    const int rq   = lane & 3;       // row pair selector

    ull acc[8][2];
#pragma unroll
    for (int i = 0; i < 8; ++i) { acc[i][0] = 0ull; acc[i][1] = 0ull; }

#pragma unroll
    for (int kc = 0; kc < 4; ++kc) {
        __syncthreads();
#pragma unroll
        for (int it = 0; it < 8; ++it) {
            int idx = tid + it * 256;                  // 0..2047
            int m = idx >> 5, kq = idx & 31;
            float4 v = *(const float4*)&h[(size_t)m * HIDD + kc * 128 + kq * 4];
            s_x[m * 32 + (kq ^ (m >> 3))] = *(ulonglong2*)&v;
        }
#pragma unroll
        for (int it = 0; it < 8; ++it) {
            int idx = tid + it * 256;
            int r = idx >> 5, kq = idx & 31;
            float4 v = *(const float4*)&w_hh[(size_t)(b2 * 64 + r) * HIDD + kc * 128 + kq * 4];
            s_w[r * 32 + (kq ^ (r & 7))] = *(ulonglong2*)&v;
        }
        __syncthreads();
#pragma unroll
        for (int q = 0; q < 32; ++q) {
            ulonglong2 xv[8], wv[2];
#pragma unroll
            for (int i = 0; i < 8; ++i) xv[i] = s_x[(mg * 8 + i) * 32 + (q ^ mg)];
#pragma unroll
            for (int j = 0; j < 2; ++j) {
                int rl = rq * 2 + j;
                wv[j] = s_w[(w * 8 + rl) * 32 + (q ^ rl)];
            }
#pragma unroll
            for (int i = 0; i < 8; ++i)
#pragma unroll
                for (int j = 0; j < 2; ++j) {
                    acc[i][j] = ffma2(xv[i].x, wv[j].x, acc[i][j]);
                    acc[i][j] = ffma2(xv[i].y, wv[j].y, acc[i][j]);
                }
        }
    }
#pragma unroll
    for (int i = 0; i < 8; ++i)
#pragma unroll
        for (int j = 0; j < 2; ++j) {
            float2 p = *(float2*)&acc[i][j];
            int R = b2 * 64 + w * 8 + rq * 2 + j;
            g_hhpart[(size_t)R * 64 + mg * 8 + i] = p.x + p.y;
        }
}

// ---------------- init (+ hh role for t=0) ----------------
#define INIT_SMEM 65536
__global__ void __launch_bounds__(256)
init_kernel(const float* __restrict__ eh, const float* __restrict__ ec,
            const int* __restrict__ tgt_i32, const float* __restrict__ w_hh) {
    extern __shared__ char smem[];
    if (blockIdx.x >= 128) {              // role blocks: W_hh @ h(0) = encoder_h
        hh_role(eh, w_hh, blockIdx.x - 128, smem);
        return;
    }
    int idx = blockIdx.x * blockDim.x + threadIdx.x;
    if (idx < BB * HIDD) {
        g_hbuf[0][idx] = eh[idx];
        g_cbuf[idx]    = ec[idx];
    }
    if (idx < TT * BB) ((ull*)g_amaxE)[idx] = 0ull;
    if (idx == 0)
        g_tmode[0] = ((tgt_i32[1] | tgt_i32[3] | tgt_i32[5] | tgt_i32[7]) == 0) ? 1 : 0;
}

// ---------------- fc_w -> fp16, 128-row chunks + swizzled --------------------
__global__ void __launch_bounds__(256) wsplit_kernel(const float* __restrict__ fc_w) {
    size_t u = (size_t)blockIdx.x * 256 + threadIdx.x;    // 0 .. 2,047,999
    int n  = (int)(u >> 6);
    int k8 = (int)(u & 63);
    const float4* src = (const float4*)(fc_w + (size_t)n * HIDD + k8 * 8);
    float4 v0 = src[0], v1 = src[1];
    float f[8] = {v0.x, v0.y, v0.z, v0.w, v1.x, v1.y, v1.z, v1.w};
    unsigned short hw[8];
#pragma unroll
    for (int i = 0; i < 8; ++i) hw[i] = __half_as_ushort(__float2half_rn(f[i]));
    uint4 H;
    H.x = hw[0] | ((uint32_t)hw[1] << 16); H.y = hw[2] | ((uint32_t)hw[3] << 16);
    H.z = hw[4] | ((uint32_t)hw[5] << 16); H.w = hw[6] | ((uint32_t)hw[7] << 16);
    int nb = n >> 7, rown = n & 127, kch = k8 >> 3, ks = k8 & 7;
    size_t cb = ((size_t)nb * 8 + kch) * 16384;
    uint32_t off = SWZ((uint32_t)(rown * 128 + ks * 16));
    *(uint4*)((char*)g_wf16 + cb + off) = H;
}

// ---------------- gates: emb GEMM + hh partials + LSTM pointwise -------------
// grid 128 (4 hidden cols -> 16 gate-rows), block 256. hh term precomputed
// into g_hhpart by fixup(t-1)/init role blocks.
#define G_SMEM_BYTES (197120 + 256)

__global__ void __launch_bounds__(256)
gates_kernel(int t,
             const long long* __restrict__ tgt64, const int* __restrict__ tgt32,
             const int* __restrict__ tf_mask,
             const float* __restrict__ emb,
             const float* __restrict__ w_ih,
             const float* __restrict__ b_ih, const float* __restrict__ b_hh) {
    extern __shared__ char smem[];
    ulonglong2* s_hx = (ulonglong2*)smem;
    ulonglong2* s_w  = (ulonglong2*)(smem + 131072);
    float (*s_part)[16][65] = (float (*)[16][65])(smem + 163840);
    int* s_inp = (int*)(smem + 197120);

    const int tid  = threadIdx.x;
    const int j0   = blockIdx.x * 4;
    const int w    = tid >> 5;
    const int lane = tid & 31;
    const int mg   = lane >> 2;
    const int rq   = lane & 3;

    if (tid < BB) {
        int inp = 0;
        if (t > 0) {
            if (tf_mask[t - 1] > 0) {
                inp = g_tmode[0] ? (int)tgt64[(size_t)tid * TT + (t - 1)]
                                 : tgt32[(size_t)tid * TT + (t - 1)];
            } else {
                ull p = g_amaxE[t - 1][tid];
                inp = (int)(0xFFFFFFFFu - (unsigned)(p & 0xFFFFFFFFull));
            }
        }
        s_inp[tid] = inp;
    }
    __syncthreads();

    ull acc[8][4];
#pragma unroll
    for (int i = 0; i < 8; ++i)
#pragma unroll
        for (int j = 0; j < 4; ++j) acc[i][j] = 0ull;

    // emb GEMM, K=256
#pragma unroll
    for (int it = 0; it < 16; ++it) {
        int idx = tid + it * 256;
        int m = idx >> 6, kq = idx & 63;
        float4 v = *(const float4*)&emb[(size_t)s_inp[m] * EMBD + kq * 4];
        s_hx[m * 64 + (kq ^ (m >> 3))] = *(ulonglong2*)&v;
    }
#pragma unroll
    for (int it = 0; it < 4; ++it) {
        int idx = tid + it * 256;
        int rr = idx >> 6, kq = idx & 63;
        int R  = (rr >> 2) * HIDD + j0 + (rr & 3);
        float4 v = *(const float4*)&w_ih[(size_t)R * EMBD + kq * 4];
        s_w[rr * 64 + (kq ^ (rr >> 2))] = *(ulonglong2*)&v;
    }
    __syncthreads();
#pragma unroll
    for (int q8 = 0; q8 < 8; ++q8) {
        int q = w * 8 + q8;
        ulonglong2 xv[8], wv[4];
#pragma unroll
        for (int i = 0; i < 8; ++i) xv[i] = s_hx[(mg * 8 + i) * 64 + (q ^ mg)];
#pragma unroll
        for (int j = 0; j < 4; ++j) wv[j] = s_w[(rq * 4 + j) * 64 + (q ^ rq)];
#pragma unroll
        for (int i = 0; i < 8; ++i)
#pragma unroll
            for (int j = 0; j < 4; ++j) {
                acc[i][j] = ffma2(xv[i].x, wv[j].x, acc[i][j]);
                acc[i][j] = ffma2(xv[i].y, wv[j].y, acc[i][j]);
            }
    }

#pragma unroll
    for (int i = 0; i < 8; ++i)
#pragma unroll
        for (int j = 0; j < 4; ++j) {
            float2 p = *(float2*)&acc[i][j];
            s_part[w][rq * 4 + j][mg * 8 + i] = p.x + p.y;
        }
    __syncthreads();

    {
        int m  = tid & 63;
        int jj = tid >> 6;
        float gv4[4];
#pragma unroll
        for (int g = 0; g < 4; ++g) {
            float s = 0.f;
#pragma unroll
            for (int w8 = 0; w8 < 8; ++w8) s += s_part[w8][g * 4 + jj][m];
            int R = g * HIDD + j0 + jj;
            gv4[g] = s + g_hhpart[(size_t)R * 64 + m] + b_ih[R] + b_hh[R];
        }
        float iv = sigm_acc(gv4[0]);
        float fv = sigm_acc(gv4[1]);
        float gg = tanh_acc(gv4[2]);
        float ov = sigm_acc(gv4[3]);
        int j = j0 + jj;
        float c0 = g_cbuf[(size_t)m * HIDD + j];
        float c1 = fv * c0 + iv * gg;
        float h1 = ov * tanh_acc(c1);
        g_cbuf[(size_t)m * HIDD + j]              = c1;
        g_hbuf[(t + 1) & 1][(size_t)m * HIDD + j] = h1;
        int kch = j >> 6, kc = j & 63, ks = kc >> 3, b2 = kc & 7;
        *(__half*)((char*)g_haf16 + (size_t)kch * 8192
                   + SWZ((uint32_t)(m * 128 + ks * 16)) + b2 * 2) = __float2half_rn(h1);
    }
}

// ---------------- fc via mma.sync fp16 (R13-proven), grid 250 ---------------
// block 256 = 8 warps (wm = w&3, wn = w>>2). 8 K-chunks of 64, 4-stage pipe.
// smem: stages [0, 4*24576) | bias @98304 | amax @98816 | mbar[4] @99328
#define FC_STG  24576
#define FC_SMEM 99392

__global__ void __launch_bounds__(256)
fc_mma_kernel(int t, const float* __restrict__ fc_b, float* __restrict__ out) {
    extern __shared__ char smem[];
    const uint32_t sbase = smem_u32(smem);
    float* s_bias = (float*)(smem + 98304);
    ull*   s_amax = (ull*)(smem + 98816);
    const uint32_t mb0 = sbase + 99328;

    const int tid  = threadIdx.x;
    const int w    = tid >> 5;
    const int lane = tid & 31;
    const int wm   = w & 3;
    const int wn   = w >> 2;
    const int nb   = blockIdx.x;
    const int row16 = lane & 15;
    const int kseg  = lane >> 4;

    if (tid < 128) s_bias[tid] = fc_b[nb * 128 + tid];
    if (tid < 64)  s_amax[tid] = 0ull;
    if (tid < 4)   MBAR_INIT(mb0 + tid * 8, 1);
    __syncthreads();
    FENCE_ASYNC();

    auto issue = [&](int c) {
        int s = c & 3;
        uint32_t mb = mb0 + s * 8;
        MBAR_EXPECT_TX(mb, 24576);
        const char* ap = (const char*)g_haf16 + (size_t)c * 8192;
        const char* wp = (const char*)g_wf16 + ((size_t)nb * 8 + c) * 16384;
        BULK_G2S(sbase + s * FC_STG, ap, 8192, mb);
        BULK_G2S(sbase + s * FC_STG + 8192, wp, 16384, mb);
    };
    if (tid == 0) { issue(0); issue(1); issue(2); issue(3); }

    float acc[8][4];
#pragma unroll
    for (int fj = 0; fj < 8; ++fj)
#pragma unroll
        for (int e = 0; e < 4; ++e) acc[fj][e] = 0.f;

    int par[4] = {0, 0, 0, 0};
    for (int c = 0; c < 8; ++c) {
        int s = c & 3;
        MBAR_WAIT(mb0 + s * 8, par[s]);
        par[s] ^= 1;
        const uint32_t aBase = sbase + s * FC_STG;
        const uint32_t wBase = aBase + 8192;
#pragma unroll
        for (int kf = 0; kf < 4; ++kf) {
            uint32_t aH[4];
            LDSM4(aH[0], aH[1], aH[2], aH[3],
                  aBase + SWZ((uint32_t)((wm * 16 + row16) * 128 + kf * 32 + kseg * 16)));
#pragma unroll
            for (int j = 0; j < 4; ++j) {
                uint32_t b[4];
                LDSM4(b[0], b[1], b[2], b[3],
                      wBase + SWZ((uint32_t)((wn * 64 + j * 16 + row16) * 128 + kf * 32 + kseg * 16)));
                MMA16816(acc[j * 2 + 0], aH, b[0], b[2]);
                MMA16816(acc[j * 2 + 1], aH, b[1], b[3]);
            }
        }
        __syncthreads();
        if (tid == 0 && c + 4 < 8) issue(c + 4);
    }

    // ---- epilogue: bias, store, per-block approx argmax keys ----
    const int r0 = wm * 16 + (lane >> 2);
    ull best0 = 0ull, best1 = 0ull;
#pragma unroll
    for (int fj = 0; fj < 8; ++fj) {
        int cb = wn * 64 + fj * 8 + (lane & 3) * 2;
        int n  = nb * 128 + cb;
        float v0 = acc[fj][0] + s_bias[cb];
        float v1 = acc[fj][1] + s_bias[cb + 1];
        float v2 = acc[fj][2] + s_bias[cb];
        float v3 = acc[fj][3] + s_bias[cb + 1];
        *(float2*)&out[((size_t)r0 * TT + t) * VOC + n]       = make_float2(v0, v1);
        *(float2*)&out[((size_t)(r0 + 8) * TT + t) * VOC + n] = make_float2(v2, v3);
        ull k0 = pack_key(v0, n), k1 = pack_key(v1, n + 1);
        ull k2 = pack_key(v2, n), k3 = pack_key(v3, n + 1);
        if (k1 > k0) k0 = k1;
        if (k3 > k2) k2 = k3;
        if (k0 > best0) best0 = k0;
        if (k2 > best1) best1 = k2;
    }
    atomicMax(&s_amax[r0], best0);
    atomicMax(&s_amax[r0 + 8], best1);
    __syncthreads();
    if (tid < 64) g_blockmax[nb][tid] = s_amax[tid];   // plain store, sole writer
}

// ---------------- fixup + hh role for next step ------------------------------
// grid 96: blocks 0..63 = argmax fixup (one per batch row),
//          blocks 64..95 = hh role (W_hh @ h(t+1) -> g_hhpart for step t+1).
#define FIX_SMEM 65536

__global__ void __launch_bounds__(256)
fixup_kernel(int t, const float* __restrict__ fc_w, const float* __restrict__ fc_b,
             const float* __restrict__ out, const float* __restrict__ w_hh) {
    extern __shared__ char dsm[];
    if (blockIdx.x >= 64) {                // hh role for step t+1
        hh_role(g_hbuf[(t + 1) & 1], w_hh, blockIdx.x - 64, dsm);
        return;
    }
    __shared__ float s_h[HIDD];
    __shared__ ull s_red[256];
    __shared__ float s_thresh;
    const int m = blockIdx.x, tid = threadIdx.x;
    const float* hsrc = g_hbuf[(t + 1) & 1] + (size_t)m * HIDD;
    s_h[tid] = hsrc[tid];
    s_h[256 + tid] = hsrc[256 + tid];

    ull key = (tid < 250) ? g_blockmax[tid][m] : 0ull;
    s_red[tid] = key;
    __syncthreads();
#pragma unroll
    for (int s = 128; s > 0; s >>= 1) {
        if (tid < s && s_red[tid + s] > s_red[tid]) s_red[tid] = s_red[tid + s];
        __syncthreads();
    }
    if (tid == 0) s_thresh = unpack_val(s_red[0]) - 1e-2f;
    __syncthreads();
    const float thresh = s_thresh;

    ull best = 0ull;
    if (tid < 250 && unpack_val(key) >= thresh) {
        const float* row = out + ((size_t)m * TT + t) * VOC + tid * 128;
#pragma unroll 4
        for (int i = 0; i < 128; ++i) {
            float v = row[i];
            if (v >= thresh) {
                int n = tid * 128 + i;
                const ull* hp = (const ull*)s_h;
                const ull* wp = (const ull*)(fc_w + (size_t)n * HIDD);
                ull acc = 0ull;
#pragma unroll 8
                for (int kk = 0; kk < 256; ++kk) acc = ffma2(hp[kk], wp[kk], acc);
                float2 p = *(float2*)&acc;
                ull k = pack_key(p.x + p.y + fc_b[n], n);
                if (k > best) best = k;
            }
        }
    }
    s_red[tid] = best;
    __syncthreads();
#pragma unroll
    for (int s = 128; s > 0; s >>= 1) {
        if (tid < s && s_red[tid + s] > s_red[tid]) s_red[tid] = s_red[tid + s];
        __syncthreads();
    }
    if (tid == 0) g_amaxE[t][m] = s_red[0];   // plain store, sole writer
}

// ---------------- final h/c tail ----------------
__global__ void final_kernel(float* __restrict__ out, int out_size) {
    int idx = blockIdx.x * blockDim.x + threadIdx.x;
    const size_t base = (size_t)BB * TT * VOC;
    if ((size_t)out_size >= base + 2ull * BB * HIDD) {
        if (idx < BB * HIDD) {
            out[base + idx]             = g_hbuf[0][idx];
            out[base + BB * HIDD + idx] = g_cbuf[idx];
        }
    }
}

// ---------------- launch ----------------
extern "C" void kernel_launch(void* const* d_in, const int* in_sizes, int n_in,
                              void* d_out, int out_size) {
    const float* encoder_h = (const float*)d_in[0];
    const float* encoder_c = (const float*)d_in[1];
    const void*  target    = d_in[2];
    const int*   tf_mask   = (const int*)d_in[3];
    const float* embedding = (const float*)d_in[4];
    const float* w_ih      = (const float*)d_in[5];
    const float* w_hh      = (const float*)d_in[6];
    const float* b_ih      = (const float*)d_in[7];
    const float* b_hh      = (const float*)d_in[8];
    const float* fc_w      = (const float*)d_in[9];
    const float* fc_b      = (const float*)d_in[10];
    float* out = (float*)d_out;

    cudaFuncSetAttribute(init_kernel,
                         cudaFuncAttributeMaxDynamicSharedMemorySize, INIT_SMEM);
    cudaFuncSetAttribute(gates_kernel,
                         cudaFuncAttributeMaxDynamicSharedMemorySize, G_SMEM_BYTES);
    cudaFuncSetAttribute(fc_mma_kernel,
                         cudaFuncAttributeMaxDynamicSharedMemorySize, FC_SMEM);
    cudaFuncSetAttribute(fixup_kernel,
                         cudaFuncAttributeMaxDynamicSharedMemorySize, FIX_SMEM);

    init_kernel<<<160, 256, INIT_SMEM>>>(encoder_h, encoder_c, (const int*)target, w_hh);
    wsplit_kernel<<<8000, 256>>>(fc_w);
    for (int t = 0; t < TT; ++t) {
        gates_kernel<<<128, 256, G_SMEM_BYTES>>>(t, (const long long*)target,
                                                 (const int*)target, tf_mask, embedding,
                                                 w_ih, b_ih, b_hh);
        fc_mma_kernel<<<250, 256, FC_SMEM>>>(t, fc_b, out);
        fixup_kernel<<<96, 256, FIX_SMEM>>>(t, fc_w, fc_b, out, w_hh);
    }
    final_kernel<<<128, 256>>>(out, out_size);
}